// round 13
// baseline (speedup 1.0000x reference)
#include <cuda_runtime.h>
#include <cstdint>
#include <math.h>

#define H 128
#define MAXB 8192
#define RPB 8                      // segments per MLP group
#define NGRP (MAXB / RPB)

__device__ int   g_starts[MAXB + 1];
__device__ float g_sent[(size_t)MAXB * H];
__device__ int   g_cnt[NGRP];

#define CP_ASYNC_CG(dst_u32, src_ptr) \
    asm volatile("cp.async.cg.shared.global [%0], [%1], 16;" :: "r"(dst_u32), "l"(src_ptr))
#define CP_COMMIT() asm volatile("cp.async.commit_group;")
#define CP_WAIT1()  asm volatile("cp.async.wait_group 1;" ::: "memory")

// ---------------------------------------------------------------------------
// Kernel 0: prepass (R9-proven). 4 tokens/thread via int4; builds g_starts,
// zeroes the output scalar and the group counters.
// ---------------------------------------------------------------------------
__global__ __launch_bounds__(256) void prepass_kernel(
    const int* __restrict__ seg_ids, float* __restrict__ out, int T, int B)
{
    const int gid = blockIdx.x * blockDim.x + threadIdx.x;
    if (gid == 0) *out = 0.0f;

    if (blockIdx.x == 0) {
        const int ngrp = (B + RPB - 1) / RPB;
        for (int g = threadIdx.x; g < ngrp; g += 256) g_cnt[g] = 0;
    }

    const int i0 = gid * 4;
    if (i0 >= T) return;

    int v[4];
    if (i0 + 3 < T) {
        const int4 q = __ldg(&((const int4*)seg_ids)[gid]);
        v[0] = q.x; v[1] = q.y; v[2] = q.z; v[3] = q.w;
    } else {
        for (int j = 0; j < 4; j++)
            v[j] = (i0 + j < T) ? __ldg(&seg_ids[i0 + j]) : v[j > 0 ? j - 1 : 0];
    }

    int prev = (i0 == 0) ? -1 : __ldg(&seg_ids[i0 - 1]);
#pragma unroll
    for (int j = 0; j < 4; j++) {
        const int i = i0 + j;
        if (i >= T) break;
        const int cur = v[j];
        for (int s = prev + 1; s <= cur; s++) g_starts[s] = i;
        if (i == T - 1)
            for (int s = cur + 1; s <= B; s++) g_starts[s] = T;
        prev = cur;
    }
}

// ---------------------------------------------------------------------------
// Kernel 1 (fused): cp.async gather + segment mean (R9-proven body); the
// LAST-arriving block of each 8-segment group runs the MLP head + BCE for
// the group (threadfence-reduction). cp.async.cg bypasses L1, so the
// CCTL.IVALL from __threadfence does not hurt the gather data path.
// Tail reuses s_buf as its transposed tile -> smem stays 18.5KB (12 blk/SM).
// ---------------------------------------------------------------------------
__global__ __launch_bounds__(128) void fused_dan_kernel(
    const int*   __restrict__ token_ids,
    const float* __restrict__ embed,
    const float* __restrict__ y_true,
    const float* __restrict__ W_hid,   // [H,H] row-major
    const float* __restrict__ b_hid,
    const float* __restrict__ W_out,
    const float* __restrict__ b_out,
    float*       __restrict__ out,
    int B)
{
    const int seg = blockIdx.x;
    const int tid = threadIdx.x;
    const int w   = tid >> 5;
    const int l   = tid & 31;

    const int start = __ldg(&g_starts[seg]);
    const int end   = __ldg(&g_starts[seg + 1]);
    const int n     = end - start;
    const int chunks = (n + 15) >> 4;

    __shared__ __align__(16) float4 s_buf[4][2][4][32];  // 16KB; reused by tail
    __shared__ float s_part[4][H];
    __shared__ int   s_last;

    const unsigned int sbase =
        (unsigned int)__cvta_generic_to_shared(&s_buf[w][0][0][l]);
    const char* E = (const char*)embed;

    float4 a0 = make_float4(0.f, 0.f, 0.f, 0.f), a1 = a0;

#define FILL(c)                                                            \
    do {                                                                   \
        const int _c = (c);                                                \
        if (_c < chunks) {                                                 \
            const int _base = start + _c * 16 + w * 4;                     \
            _Pragma("unroll")                                              \
            for (int _j = 0; _j < 4; _j++) {                               \
                const int _idx = _base + _j;                               \
                if (_idx < end) {                                          \
                    const int _tok = __ldg(&token_ids[_idx]);              \
                    CP_ASYNC_CG(sbase + (unsigned int)((_c & 1) * 2048 + _j * 512), \
                                E + (size_t)_tok * 512 + l * 16);          \
                }                                                          \
            }                                                              \
        }                                                                  \
        CP_COMMIT();                                                       \
    } while (0)

    FILL(0);
    FILL(1);

    for (int c = 0; c < chunks; c++) {
        CP_WAIT1();
        const int base = c * 16 + w * 4;
        const int m    = n - base;
        const int slot = c & 1;
        if (m >= 1) { const float4 v = s_buf[w][slot][0][l];
                      a0.x += v.x; a0.y += v.y; a0.z += v.z; a0.w += v.w; }
        if (m >= 2) { const float4 v = s_buf[w][slot][1][l];
                      a1.x += v.x; a1.y += v.y; a1.z += v.z; a1.w += v.w; }
        if (m >= 3) { const float4 v = s_buf[w][slot][2][l];
                      a0.x += v.x; a0.y += v.y; a0.z += v.z; a0.w += v.w; }
        if (m >= 4) { const float4 v = s_buf[w][slot][3][l];
                      a1.x += v.x; a1.y += v.y; a1.z += v.z; a1.w += v.w; }
        FILL(c + 2);
    }
#undef FILL

    float4 asum;
    asum.x = a0.x + a1.x;  asum.y = a0.y + a1.y;
    asum.z = a0.z + a1.z;  asum.w = a0.w + a1.w;
    *(float4*)&s_part[w][4 * l] = asum;
    __syncthreads();

    const float inv = 1.0f / (float)max(n, 1);
    g_sent[(size_t)seg * H + tid] =
        ((s_part[0][tid] + s_part[1][tid]) +
         (s_part[2][tid] + s_part[3][tid])) * inv;

    // ---- group rendezvous ----
    const int grp = seg / RPB;
    __threadfence();                          // release g_sent row
    if (tid == 0)
        s_last = (atomicAdd(&g_cnt[grp], 1) == RPB - 1);
    __syncthreads();
    if (!s_last) return;
    __threadfence();                          // acquire peers' g_sent rows

    // ---- tail MLP + BCE for rows grp*RPB .. grp*RPB+7 ----
    float (*s_t)[RPB] = reinterpret_cast<float (*)[RPB]>(&s_buf[0][0][0][0]);
    const int row0 = grp * RPB;
#pragma unroll
    for (int r = 0; r < RPB; r++) {
        const int row = min(row0 + r, B - 1);
        s_t[tid][r] = __ldg(&g_sent[(size_t)row * H + tid]);
    }
    __syncthreads();

    float acc[RPB];
    const float bh = b_hid[tid];
#pragma unroll
    for (int r = 0; r < RPB; r++) acc[r] = bh;

#pragma unroll 4
    for (int k = 0; k < H; k++) {
        const float  wv = __ldg(&W_hid[k * H + tid]);
        const float4 sa = *(const float4*)&s_t[k][0];   // broadcast LDS.128
        const float4 sb = *(const float4*)&s_t[k][4];
        acc[0] += sa.x * wv;  acc[1] += sa.y * wv;
        acc[2] += sa.z * wv;  acc[3] += sa.w * wv;
        acc[4] += sb.x * wv;  acc[5] += sb.y * wv;
        acc[6] += sb.z * wv;  acc[7] += sb.w * wv;
    }

    const float wo = W_out[tid];
    float val[RPB];
#pragma unroll
    for (int r = 0; r < RPB; r++)
        val[r] = tanhf(acc[r]) * wo;

#pragma unroll
    for (int off = 16; off > 0; off >>= 1)
#pragma unroll
        for (int r = 0; r < RPB; r++)
            val[r] += __shfl_xor_sync(0xffffffffu, val[r], off);

    __syncthreads();                          // s_t reuse as reduction scratch
    if (l == 0)
#pragma unroll
        for (int r = 0; r < RPB; r++) s_t[r][w] = val[r];
    __syncthreads();

    if (tid < RPB) {
        const int row = row0 + tid;
        float loss = 0.f;
        if (row < B) {
            const float z = (s_t[tid][0] + s_t[tid][1]) +
                            (s_t[tid][2] + s_t[tid][3]) + __ldg(b_out);
            const float lp  = fmaxf(-log1pf(expf(-z)), -100.0f);
            const float l1m = fmaxf(-log1pf(expf(z)),  -100.0f);
            const float y   = __ldg(&y_true[row]);
            loss = -(y * lp + (1.0f - y) * l1m);
        }
#pragma unroll
        for (int off = 4; off > 0; off >>= 1)
            loss += __shfl_xor_sync(0x000000ffu, loss, off);
        if (tid == 0) atomicAdd(out, loss);
    }
}

// ---------------------------------------------------------------------------
extern "C" void kernel_launch(void* const* d_in, const int* in_sizes, int n_in,
                              void* d_out, int out_size)
{
    const int*   token_ids = (const int*)d_in[0];
    const int*   seg_ids   = (const int*)d_in[1];
    const float* y_true    = (const float*)d_in[2];
    const float* embed     = (const float*)d_in[3];
    const float* W_hid     = (const float*)d_in[4];
    const float* b_hid     = (const float*)d_in[5];
    const float* W_out     = (const float*)d_in[6];
    const float* b_out     = (const float*)d_in[7];

    const int T = in_sizes[0];
    const int B = in_sizes[2];
    float* out = (float*)d_out;

    const int vthreads = (T + 3) / 4;
    prepass_kernel<<<(vthreads + 255) / 256, 256>>>(seg_ids, out, T, B);

    fused_dan_kernel<<<B, 128>>>(token_ids, embed, y_true,
                                 W_hid, b_hid, W_out, b_out, out, B);
}

// round 14
// speedup vs baseline: 1.1055x; 1.1055x over previous
#include <cuda_runtime.h>
#include <cstdint>
#include <math.h>

#define H 128
#define MAXB 8192
#define RPB 4   // rows per MLP block

__device__ int   g_starts[MAXB + 1];
__device__ float g_sent[(size_t)MAXB * H];
__device__ int   g_done;          // zero-init; reset by MLP kernel each call

#define CP_ASYNC_CG(dst_u32, src_ptr) \
    asm volatile("cp.async.cg.shared.global [%0], [%1], 16;" :: "r"(dst_u32), "l"(src_ptr))
#define CP_COMMIT() asm volatile("cp.async.commit_group;")
#define CP_WAIT1()  asm volatile("cp.async.wait_group 1;" ::: "memory")

// ---------------------------------------------------------------------------
// Kernel 1: prepass (blocks 0..npre-1) + spin gate + cp.async gather/mean.
// Prepass blocks build g_starts (R9 logic), then release-add g_done.
// Every block's thread 0 acquire-spins until g_done == npre, then the block
// gathers its segment with the R9-proven warp-private cp.async pipeline.
// First wave (~12 blk/SM * 148 = ~1776) >= npre=400, so all prepass blocks
// are resident immediately -> no deadlock.
// ---------------------------------------------------------------------------
__global__ __launch_bounds__(128) void gather_kernel(
    const int*   __restrict__ token_ids,
    const int*   __restrict__ seg_ids,
    const float* __restrict__ embed,
    float*       __restrict__ out,
    int T, int B, int npre)
{
    const int seg = blockIdx.x;
    const int tid = threadIdx.x;
    const int w   = tid >> 5;
    const int l   = tid & 31;

    __shared__ __align__(16) float4 s_buf[4][2][4][32];  // [warp][slot][row][lane]
    __shared__ float s_part[4][H];

    // ---- prepass: blocks 0..npre-1, 4 tokens per thread per 2 sub-slices ----
    if (seg < npre) {
        if (seg == 0 && tid == 0) *out = 0.0f;
        // this block covers tokens [seg*1024, seg*1024+1024) via 256 virtual
        // threads of 4 tokens; our 128 threads each take 2 virtual slots.
        for (int sub = 0; sub < 2; sub++) {
            const int vt = seg * 256 + sub * 128 + tid;
            const int i0 = vt * 4;
            if (i0 < T) {
                int v[4];
                if (i0 + 3 < T) {
                    const int4 q = __ldg(&((const int4*)seg_ids)[vt]);
                    v[0] = q.x; v[1] = q.y; v[2] = q.z; v[3] = q.w;
                } else {
                    for (int j = 0; j < 4; j++)
                        v[j] = (i0 + j < T) ? __ldg(&seg_ids[i0 + j])
                                            : v[j > 0 ? j - 1 : 0];
                }
                int prev = (i0 == 0) ? -1 : __ldg(&seg_ids[i0 - 1]);
#pragma unroll
                for (int j = 0; j < 4; j++) {
                    const int i = i0 + j;
                    if (i >= T) break;
                    const int cur = v[j];
                    for (int s = prev + 1; s <= cur; s++) g_starts[s] = i;
                    if (i == T - 1)
                        for (int s = cur + 1; s <= B; s++) g_starts[s] = T;
                    prev = cur;
                }
            }
        }
        __syncthreads();
        if (tid == 0) {
            int* p = &g_done;
            asm volatile("red.release.gpu.global.add.s32 [%0], 1;" :: "l"(p));
        }
    }

    // ---- spin gate: wait until all prepass blocks released ----
    if (tid == 0) {
        int* p = &g_done;
        int d;
        do {
            asm volatile("ld.acquire.gpu.global.s32 %0, [%1];"
                         : "=r"(d) : "l"(p));
            if (d < npre) __nanosleep(64);
        } while (d < npre);
    }
    __syncthreads();

    // ---- gather + mean (R9-proven body) ----
    const int start = g_starts[seg];
    const int end   = g_starts[seg + 1];
    const int n     = end - start;
    const int chunks = (n + 15) >> 4;

    const unsigned int sbase =
        (unsigned int)__cvta_generic_to_shared(&s_buf[w][0][0][l]);
    const char* E = (const char*)embed;

    float4 a0 = make_float4(0.f, 0.f, 0.f, 0.f), a1 = a0;

#define FILL(c)                                                            \
    do {                                                                   \
        const int _c = (c);                                                \
        if (_c < chunks) {                                                 \
            const int _base = start + _c * 16 + w * 4;                     \
            _Pragma("unroll")                                              \
            for (int _j = 0; _j < 4; _j++) {                               \
                const int _idx = _base + _j;                               \
                if (_idx < end) {                                          \
                    const int _tok = __ldg(&token_ids[_idx]);              \
                    CP_ASYNC_CG(sbase + (unsigned int)((_c & 1) * 2048 + _j * 512), \
                                E + (size_t)_tok * 512 + l * 16);          \
                }                                                          \
            }                                                              \
        }                                                                  \
        CP_COMMIT();                                                       \
    } while (0)

    FILL(0);
    FILL(1);

    for (int c = 0; c < chunks; c++) {
        CP_WAIT1();
        const int base = c * 16 + w * 4;
        const int m    = n - base;
        const int slot = c & 1;
        if (m >= 1) { const float4 v = s_buf[w][slot][0][l];
                      a0.x += v.x; a0.y += v.y; a0.z += v.z; a0.w += v.w; }
        if (m >= 2) { const float4 v = s_buf[w][slot][1][l];
                      a1.x += v.x; a1.y += v.y; a1.z += v.z; a1.w += v.w; }
        if (m >= 3) { const float4 v = s_buf[w][slot][2][l];
                      a0.x += v.x; a0.y += v.y; a0.z += v.z; a0.w += v.w; }
        if (m >= 4) { const float4 v = s_buf[w][slot][3][l];
                      a1.x += v.x; a1.y += v.y; a1.z += v.z; a1.w += v.w; }
        FILL(c + 2);
    }
#undef FILL

    float4 asum;
    asum.x = a0.x + a1.x;  asum.y = a0.y + a1.y;
    asum.z = a0.z + a1.z;  asum.w = a0.w + a1.w;
    *(float4*)&s_part[w][4 * l] = asum;
    __syncthreads();

    const float inv = 1.0f / (float)max(n, 1);
    g_sent[(size_t)seg * H + tid] =
        ((s_part[0][tid] + s_part[1][tid]) +
         (s_part[2][tid] + s_part[3][tid])) * inv;
}

// ---------------------------------------------------------------------------
// Kernel 2: MLP head + BCE. 4 rows per 256-thread block (grid=1024 -> ~7
// blocks/SM, ~55 warps), 2-way k-split. Block 0 resets the spin gate for
// the next graph replay.
// ---------------------------------------------------------------------------
__global__ __launch_bounds__(256) void mlp_bce_kernel(
    const float* __restrict__ y_true,
    const float* __restrict__ W_hid,   // [H,H] row-major
    const float* __restrict__ b_hid,
    const float* __restrict__ W_out,
    const float* __restrict__ b_out,
    float*       __restrict__ out,
    int B)
{
    const int t    = threadIdx.x;
    const int row0 = blockIdx.x * RPB;
    const int kh   = t >> 7;           // k-half
    const int col  = t & 127;

    if (blockIdx.x == 0 && t == 0) g_done = 0;   // reset gate for next replay

    __shared__ float s_t[H][RPB];      // transposed sentence tile (2KB)
    __shared__ float s_p[2][RPB][H];   // per-half partials (4KB)
    __shared__ float red[RPB][4];

#pragma unroll
    for (int e = t; e < RPB * H; e += 256) {
        const int r = e >> 7;
        const int k = e & 127;
        const int row = min(row0 + r, B - 1);
        s_t[k][r] = g_sent[(size_t)row * H + k];
    }
    __syncthreads();

    float acc[RPB];
#pragma unroll
    for (int r = 0; r < RPB; r++) acc[r] = 0.f;

    const int k0 = kh * 64;
#pragma unroll 4
    for (int kk = 0; kk < 64; kk++) {
        const int k = k0 + kk;
        const float  wv = __ldg(&W_hid[k * H + col]);
        const float4 sa = *(const float4*)&s_t[k][0];   // broadcast LDS.128
        acc[0] += sa.x * wv;  acc[1] += sa.y * wv;
        acc[2] += sa.z * wv;  acc[3] += sa.w * wv;
    }
#pragma unroll
    for (int r = 0; r < RPB; r++) s_p[kh][r][col] = acc[r];
    __syncthreads();

    if (t < 128) {
        const float bh = b_hid[col];
        const float wo = W_out[col];
        float val[RPB];
#pragma unroll
        for (int r = 0; r < RPB; r++)
            val[r] = tanhf(s_p[0][r][col] + s_p[1][r][col] + bh) * wo;

#pragma unroll
        for (int off = 16; off > 0; off >>= 1)
#pragma unroll
            for (int r = 0; r < RPB; r++)
                val[r] += __shfl_xor_sync(0xffffffffu, val[r], off);

        if ((t & 31) == 0)
#pragma unroll
            for (int r = 0; r < RPB; r++) red[r][t >> 5] = val[r];
    }
    __syncthreads();

    if (t < RPB) {
        const int row = row0 + t;
        float loss = 0.f;
        if (row < B) {
            const float z = (red[t][0] + red[t][1]) +
                            (red[t][2] + red[t][3]) + __ldg(b_out);
            const float lp  = fmaxf(-log1pf(expf(-z)), -100.0f);
            const float l1m = fmaxf(-log1pf(expf(z)),  -100.0f);
            const float y   = __ldg(&y_true[row]);
            loss = -(y * lp + (1.0f - y) * l1m);
        }
#pragma unroll
        for (int off = 2; off > 0; off >>= 1)
            loss += __shfl_xor_sync(0x0000000fu, loss, off);
        if (t == 0) atomicAdd(out, loss);
    }
}

// ---------------------------------------------------------------------------
extern "C" void kernel_launch(void* const* d_in, const int* in_sizes, int n_in,
                              void* d_out, int out_size)
{
    const int*   token_ids = (const int*)d_in[0];
    const int*   seg_ids   = (const int*)d_in[1];
    const float* y_true    = (const float*)d_in[2];
    const float* embed     = (const float*)d_in[3];
    const float* W_hid     = (const float*)d_in[4];
    const float* b_hid     = (const float*)d_in[5];
    const float* W_out     = (const float*)d_in[6];
    const float* b_out     = (const float*)d_in[7];

    const int T = in_sizes[0];
    const int B = in_sizes[2];
    float* out = (float*)d_out;

    const int npre = (T + 1023) / 1024;   // prepass blocks (each covers 1024 tokens)

    gather_kernel<<<B, 128>>>(token_ids, seg_ids, embed, out, T, B, npre);

    mlp_bce_kernel<<<(B + RPB - 1) / RPB, 256>>>(y_true, W_hid, b_hid,
                                                 W_out, b_out, out, B);
}

// round 15
// speedup vs baseline: 1.3435x; 1.2152x over previous
#include <cuda_runtime.h>
#include <cstdint>
#include <math.h>

#define H 128
#define MAXB 8192
#define RPB 4   // rows per MLP block

__device__ int   g_starts[MAXB + 1];
__device__ float g_sent[(size_t)MAXB * H];

#define CP_ASYNC_CG(dst_u32, src_ptr) \
    asm volatile("cp.async.cg.shared.global [%0], [%1], 16;" :: "r"(dst_u32), "l"(src_ptr))
#define CP_COMMIT() asm volatile("cp.async.commit_group;")
#define CP_WAIT1()  asm volatile("cp.async.wait_group 1;" ::: "memory")

// ---------------------------------------------------------------------------
// Kernel 0: prepass (R9-proven, unchanged). 4 tokens/thread via int4; builds
// g_starts from sorted segment_ids and zeroes the output scalar.
// ---------------------------------------------------------------------------
__global__ __launch_bounds__(256) void prepass_kernel(
    const int* __restrict__ seg_ids, float* __restrict__ out, int T, int B)
{
    const int gid = blockIdx.x * blockDim.x + threadIdx.x;
    if (gid == 0) *out = 0.0f;

    const int i0 = gid * 4;
    if (i0 >= T) return;

    int v[4];
    if (i0 + 3 < T) {
        const int4 q = __ldg(&((const int4*)seg_ids)[gid]);
        v[0] = q.x; v[1] = q.y; v[2] = q.z; v[3] = q.w;
    } else {
        for (int j = 0; j < 4; j++)
            v[j] = (i0 + j < T) ? __ldg(&seg_ids[i0 + j]) : v[j > 0 ? j - 1 : 0];
    }

    int prev = (i0 == 0) ? -1 : __ldg(&seg_ids[i0 - 1]);
#pragma unroll
    for (int j = 0; j < 4; j++) {
        const int i = i0 + j;
        if (i >= T) break;
        const int cur = v[j];
        for (int s = prev + 1; s <= cur; s++) g_starts[s] = i;
        if (i == T - 1)
            for (int s = cur + 1; s <= B; s++) g_starts[s] = T;
        prev = cur;
    }
}

// ---------------------------------------------------------------------------
// Kernel 1: gather + segment mean via cp.async double-buffering (R9-proven,
// unchanged). One CTA per segment; warp-private pipeline, no mainloop
// barriers.
// ---------------------------------------------------------------------------
__global__ __launch_bounds__(128) void seg_mean_kernel(
    const int*   __restrict__ token_ids,
    const float* __restrict__ embed)
{
    const int seg = blockIdx.x;
    const int tid = threadIdx.x;
    const int w   = tid >> 5;
    const int l   = tid & 31;

    const int start = __ldg(&g_starts[seg]);
    const int end   = __ldg(&g_starts[seg + 1]);
    const int n     = end - start;
    const int chunks = (n + 15) >> 4;

    __shared__ __align__(16) float4 s_buf[4][2][4][32];  // [warp][slot][row][lane]
    __shared__ float s_part[4][H];

    const unsigned int sbase =
        (unsigned int)__cvta_generic_to_shared(&s_buf[w][0][0][l]);
    const char* E = (const char*)embed;

    float4 a0 = make_float4(0.f, 0.f, 0.f, 0.f), a1 = a0;

#define FILL(c)                                                            \
    do {                                                                   \
        const int _c = (c);                                                \
        if (_c < chunks) {                                                 \
            const int _base = start + _c * 16 + w * 4;                     \
            _Pragma("unroll")                                              \
            for (int _j = 0; _j < 4; _j++) {                               \
                const int _idx = _base + _j;                               \
                if (_idx < end) {                                          \
                    const int _tok = __ldg(&token_ids[_idx]);              \
                    CP_ASYNC_CG(sbase + (unsigned int)((_c & 1) * 2048 + _j * 512), \
                                E + (size_t)_tok * 512 + l * 16);          \
                }                                                          \
            }                                                              \
        }                                                                  \
        CP_COMMIT();                                                       \
    } while (0)

    FILL(0);
    FILL(1);

    for (int c = 0; c < chunks; c++) {
        CP_WAIT1();
        const int base = c * 16 + w * 4;
        const int m    = n - base;
        const int slot = c & 1;
        if (m >= 1) { const float4 v = s_buf[w][slot][0][l];
                      a0.x += v.x; a0.y += v.y; a0.z += v.z; a0.w += v.w; }
        if (m >= 2) { const float4 v = s_buf[w][slot][1][l];
                      a1.x += v.x; a1.y += v.y; a1.z += v.z; a1.w += v.w; }
        if (m >= 3) { const float4 v = s_buf[w][slot][2][l];
                      a0.x += v.x; a0.y += v.y; a0.z += v.z; a0.w += v.w; }
        if (m >= 4) { const float4 v = s_buf[w][slot][3][l];
                      a1.x += v.x; a1.y += v.y; a1.z += v.z; a1.w += v.w; }
        FILL(c + 2);
    }
#undef FILL

    float4 asum;
    asum.x = a0.x + a1.x;  asum.y = a0.y + a1.y;
    asum.z = a0.z + a1.z;  asum.w = a0.w + a1.w;
    *(float4*)&s_part[w][4 * l] = asum;
    __syncthreads();

    const float inv = 1.0f / (float)max(n, 1);
    g_sent[(size_t)seg * H + tid] =
        ((s_part[0][tid] + s_part[1][tid]) +
         (s_part[2][tid] + s_part[3][tid])) * inv;
}

// ---------------------------------------------------------------------------
// Kernel 2: MLP head + BCE, vectorized. 4 rows per 256-thread block
// (grid=1024). 8-way k-split: warp kg covers k in [16kg, 16kg+16); lane c
// owns output cols 4c..4c+3. Mainloop iteration = 1 coalesced LDG.128 (W)
// + 1 broadcast LDS.128 (s_t row) + 16 FMA with 16 independent chains.
// ---------------------------------------------------------------------------
__global__ __launch_bounds__(256) void mlp_bce_kernel(
    const float* __restrict__ y_true,
    const float* __restrict__ W_hid,   // [H,H] row-major
    const float* __restrict__ b_hid,
    const float* __restrict__ W_out,
    const float* __restrict__ b_out,
    float*       __restrict__ out,
    int B)
{
    const int t    = threadIdx.x;
    const int row0 = blockIdx.x * RPB;
    const int kg   = t >> 5;           // k-group 0..7 (== warp id)
    const int c    = t & 31;           // col group: cols 4c..4c+3

    __shared__ __align__(16) float s_t[H][RPB];   // [k][row] tile (2KB)
    __shared__ __align__(16) float s_p[8][RPB][H]; // [kg][row][col] (16KB)
    __shared__ float red[RPB][4];

#pragma unroll
    for (int e = t; e < RPB * H; e += 256) {
        const int r = e >> 7;
        const int k = e & 127;
        const int row = min(row0 + r, B - 1);
        s_t[k][r] = g_sent[(size_t)row * H + k];
    }
    __syncthreads();

    const float4* W4 = (const float4*)W_hid;   // W4[k*32 + c] = W[k][4c..4c+3]

    float4 acc[RPB];
#pragma unroll
    for (int r = 0; r < RPB; r++) acc[r] = make_float4(0.f, 0.f, 0.f, 0.f);

#pragma unroll
    for (int kk = 0; kk < 16; kk++) {
        const int k = kg * 16 + kk;
        const float4 wv = __ldg(&W4[k * 32 + c]);
        const float4 s4 = *(const float4*)&s_t[k][0];   // rows 0..3, broadcast
        acc[0].x += s4.x * wv.x; acc[0].y += s4.x * wv.y;
        acc[0].z += s4.x * wv.z; acc[0].w += s4.x * wv.w;
        acc[1].x += s4.y * wv.x; acc[1].y += s4.y * wv.y;
        acc[1].z += s4.y * wv.z; acc[1].w += s4.y * wv.w;
        acc[2].x += s4.z * wv.x; acc[2].y += s4.z * wv.y;
        acc[2].z += s4.z * wv.z; acc[2].w += s4.z * wv.w;
        acc[3].x += s4.w * wv.x; acc[3].y += s4.w * wv.y;
        acc[3].z += s4.w * wv.z; acc[3].w += s4.w * wv.w;
    }
#pragma unroll
    for (int r = 0; r < RPB; r++)
        *(float4*)&s_p[kg][r][4 * c] = acc[r];
    __syncthreads();

    if (t < 128) {                     // 4 warps: col = t
        const int col = t;
        const float bh = b_hid[col];
        const float wo = W_out[col];
        float val[RPB];
#pragma unroll
        for (int r = 0; r < RPB; r++) {
            float s = bh;
#pragma unroll
            for (int g = 0; g < 8; g++) s += s_p[g][r][col];
            val[r] = tanhf(s) * wo;
        }
#pragma unroll
        for (int off = 16; off > 0; off >>= 1)
#pragma unroll
            for (int r = 0; r < RPB; r++)
                val[r] += __shfl_xor_sync(0xffffffffu, val[r], off);

        if ((t & 31) == 0)
#pragma unroll
            for (int r = 0; r < RPB; r++) red[r][t >> 5] = val[r];
    }
    __syncthreads();

    if (t < RPB) {
        const int row = row0 + t;
        float loss = 0.f;
        if (row < B) {
            const float z = (red[t][0] + red[t][1]) +
                            (red[t][2] + red[t][3]) + __ldg(b_out);
            const float lp  = fmaxf(-log1pf(expf(-z)), -100.0f);
            const float l1m = fmaxf(-log1pf(expf(z)),  -100.0f);
            const float y   = __ldg(&y_true[row]);
            loss = -(y * lp + (1.0f - y) * l1m);
        }
#pragma unroll
        for (int off = 2; off > 0; off >>= 1)
            loss += __shfl_xor_sync(0x0000000fu, loss, off);
        if (t == 0) atomicAdd(out, loss);
    }
}

// ---------------------------------------------------------------------------
extern "C" void kernel_launch(void* const* d_in, const int* in_sizes, int n_in,
                              void* d_out, int out_size)
{
    const int*   token_ids = (const int*)d_in[0];
    const int*   seg_ids   = (const int*)d_in[1];
    const float* y_true    = (const float*)d_in[2];
    const float* embed     = (const float*)d_in[3];
    const float* W_hid     = (const float*)d_in[4];
    const float* b_hid     = (const float*)d_in[5];
    const float* W_out     = (const float*)d_in[6];
    const float* b_out     = (const float*)d_in[7];

    const int T = in_sizes[0];
    const int B = in_sizes[2];
    float* out = (float*)d_out;

    const int vthreads = (T + 3) / 4;
    prepass_kernel<<<(vthreads + 255) / 256, 256>>>(seg_ids, out, T, B);

    seg_mean_kernel<<<B, 128>>>(token_ids, embed);

    mlp_bce_kernel<<<(B + RPB - 1) / RPB, 256>>>(y_true, W_hid, b_hid,
                                                 W_out, b_out, out, B);
}

// round 16
// speedup vs baseline: 1.3568x; 1.0099x over previous
#include <cuda_runtime.h>
#include <cstdint>
#include <math.h>

#define H 128
#define MAXB 8192
#define RPB 4   // rows per MLP block

__device__ float g_sent[(size_t)MAXB * H];

#define CP_ASYNC_CG(dst_u32, src_ptr) \
    asm volatile("cp.async.cg.shared.global [%0], [%1], 16;" :: "r"(dst_u32), "l"(src_ptr))
#define CP_COMMIT() asm volatile("cp.async.commit_group;")
#define CP_WAIT1()  asm volatile("cp.async.wait_group 1;" ::: "memory")

// ---------------------------------------------------------------------------
// Warp-parallel 32-ary lower_bound over sorted a[0..T): first i with a[i]>=key.
// 3-4 dependent probe rounds (vs ~19 for binary search). Level-1 probe
// addresses are identical across all blocks -> L2-hot.
// All 32 lanes of the calling warp must participate.
// ---------------------------------------------------------------------------
__device__ __forceinline__ int lower_bound32(
    const int* __restrict__ a, int T, int key)
{
    const int lane = threadIdx.x & 31;
    int lo = 0, hi = T;                      // answer in [lo, hi]
    while (hi - lo > 32) {
        const int span = hi - lo;
        const int p = lo + (span * (lane + 1)) / 33;   // p in [lo+1, hi-1]
        const bool lt = (__ldg(&a[p]) < key);
        const unsigned m = __ballot_sync(0xffffffffu, lt);
        const int k = __popc(m);             // prefix length of (< key) probes
        const int nhi = (k == 32) ? hi : lo + (span * (k + 1)) / 33;
        lo = (k == 0) ? lo : lo + (span * k) / 33 + 1;
        hi = nhi;
    }
    const int p = lo + lane;
    const bool lt = (p < hi) ? (__ldg(&a[p]) < key) : false;
    return lo + __popc(__ballot_sync(0xffffffffu, lt));
}

// ---------------------------------------------------------------------------
// Kernel 1: gather + segment mean. One CTA per segment. Segment bounds via
// warp-parallel p-ary search (warp 0 -> start, warp 1 -> end; ~4 L2 rounds
// each, run concurrently). Then the R9-proven cp.async double-buffered
// warp-private gather pipeline (no mainloop barriers).
// ---------------------------------------------------------------------------
__global__ __launch_bounds__(128) void seg_mean_kernel(
    const int*   __restrict__ token_ids,
    const int*   __restrict__ seg_ids,
    const float* __restrict__ embed,
    float*       __restrict__ out,
    int T)
{
    const int seg = blockIdx.x;
    const int tid = threadIdx.x;
    const int w   = tid >> 5;
    const int l   = tid & 31;

    if (seg == 0 && tid == 0) *out = 0.0f;   // harness poisons d_out

    __shared__ __align__(16) float4 s_buf[4][2][4][32];  // [warp][slot][row][lane]
    __shared__ float s_part[4][H];
    __shared__ int   s_bounds[2];

    if (w == 0) {
        const int v = lower_bound32(seg_ids, T, seg);
        if (l == 0) s_bounds[0] = v;
    } else if (w == 1) {
        const int v = lower_bound32(seg_ids, T, seg + 1);
        if (l == 0) s_bounds[1] = v;
    }
    __syncthreads();

    const int start = s_bounds[0];
    const int end   = s_bounds[1];
    const int n     = end - start;
    const int chunks = (n + 15) >> 4;

    const unsigned int sbase =
        (unsigned int)__cvta_generic_to_shared(&s_buf[w][0][0][l]);
    const char* E = (const char*)embed;

    float4 a0 = make_float4(0.f, 0.f, 0.f, 0.f), a1 = a0;

#define FILL(c)                                                            \
    do {                                                                   \
        const int _c = (c);                                                \
        if (_c < chunks) {                                                 \
            const int _base = start + _c * 16 + w * 4;                     \
            _Pragma("unroll")                                              \
            for (int _j = 0; _j < 4; _j++) {                               \
                const int _idx = _base + _j;                               \
                if (_idx < end) {                                          \
                    const int _tok = __ldg(&token_ids[_idx]);              \
                    CP_ASYNC_CG(sbase + (unsigned int)((_c & 1) * 2048 + _j * 512), \
                                E + (size_t)_tok * 512 + l * 16);          \
                }                                                          \
            }                                                              \
        }                                                                  \
        CP_COMMIT();                                                       \
    } while (0)

    FILL(0);
    FILL(1);

    for (int c = 0; c < chunks; c++) {
        CP_WAIT1();
        const int base = c * 16 + w * 4;
        const int m    = n - base;
        const int slot = c & 1;
        if (m >= 1) { const float4 v = s_buf[w][slot][0][l];
                      a0.x += v.x; a0.y += v.y; a0.z += v.z; a0.w += v.w; }
        if (m >= 2) { const float4 v = s_buf[w][slot][1][l];
                      a1.x += v.x; a1.y += v.y; a1.z += v.z; a1.w += v.w; }
        if (m >= 3) { const float4 v = s_buf[w][slot][2][l];
                      a0.x += v.x; a0.y += v.y; a0.z += v.z; a0.w += v.w; }
        if (m >= 4) { const float4 v = s_buf[w][slot][3][l];
                      a1.x += v.x; a1.y += v.y; a1.z += v.z; a1.w += v.w; }
        FILL(c + 2);
    }
#undef FILL

    float4 asum;
    asum.x = a0.x + a1.x;  asum.y = a0.y + a1.y;
    asum.z = a0.z + a1.z;  asum.w = a0.w + a1.w;
    *(float4*)&s_part[w][4 * l] = asum;
    __syncthreads();

    const float inv = 1.0f / (float)max(n, 1);
    g_sent[(size_t)seg * H + tid] =
        ((s_part[0][tid] + s_part[1][tid]) +
         (s_part[2][tid] + s_part[3][tid])) * inv;
}

// ---------------------------------------------------------------------------
// Kernel 2: MLP head + BCE, vectorized (R15). 4 rows per 256-thread block
// (grid=1024). 8-way k-split: warp kg covers k in [16kg, 16kg+16); lane c
// owns output cols 4c..4c+3. Mainloop iteration = 1 coalesced LDG.128 (W)
// + 1 broadcast LDS.128 + 16 FMA with 16 independent chains.
// ---------------------------------------------------------------------------
__global__ __launch_bounds__(256) void mlp_bce_kernel(
    const float* __restrict__ y_true,
    const float* __restrict__ W_hid,   // [H,H] row-major
    const float* __restrict__ b_hid,
    const float* __restrict__ W_out,
    const float* __restrict__ b_out,
    float*       __restrict__ out,
    int B)
{
    const int t    = threadIdx.x;
    const int row0 = blockIdx.x * RPB;
    const int kg   = t >> 5;           // k-group 0..7 (== warp id)
    const int c    = t & 31;           // col group: cols 4c..4c+3

    __shared__ __align__(16) float s_t[H][RPB];    // [k][row] tile (2KB)
    __shared__ __align__(16) float s_p[8][RPB][H]; // [kg][row][col] (16KB)
    __shared__ float red[RPB][4];

#pragma unroll
    for (int e = t; e < RPB * H; e += 256) {
        const int r = e >> 7;
        const int k = e & 127;
        const int row = min(row0 + r, B - 1);
        s_t[k][r] = g_sent[(size_t)row * H + k];
    }
    __syncthreads();

    const float4* W4 = (const float4*)W_hid;   // W4[k*32 + c] = W[k][4c..4c+3]

    float4 acc[RPB];
#pragma unroll
    for (int r = 0; r < RPB; r++) acc[r] = make_float4(0.f, 0.f, 0.f, 0.f);

#pragma unroll
    for (int kk = 0; kk < 16; kk++) {
        const int k = kg * 16 + kk;
        const float4 wv = __ldg(&W4[k * 32 + c]);
        const float4 s4 = *(const float4*)&s_t[k][0];   // rows 0..3, broadcast
        acc[0].x += s4.x * wv.x; acc[0].y += s4.x * wv.y;
        acc[0].z += s4.x * wv.z; acc[0].w += s4.x * wv.w;
        acc[1].x += s4.y * wv.x; acc[1].y += s4.y * wv.y;
        acc[1].z += s4.y * wv.z; acc[1].w += s4.y * wv.w;
        acc[2].x += s4.z * wv.x; acc[2].y += s4.z * wv.y;
        acc[2].z += s4.z * wv.z; acc[2].w += s4.z * wv.w;
        acc[3].x += s4.w * wv.x; acc[3].y += s4.w * wv.y;
        acc[3].z += s4.w * wv.z; acc[3].w += s4.w * wv.w;
    }
#pragma unroll
    for (int r = 0; r < RPB; r++)
        *(float4*)&s_p[kg][r][4 * c] = acc[r];
    __syncthreads();

    if (t < 128) {                     // 4 warps: col = t
        const int col = t;
        const float bh = b_hid[col];
        const float wo = W_out[col];
        float val[RPB];
#pragma unroll
        for (int r = 0; r < RPB; r++) {
            float s = bh;
#pragma unroll
            for (int g = 0; g < 8; g++) s += s_p[g][r][col];
            val[r] = tanhf(s) * wo;
        }
#pragma unroll
        for (int off = 16; off > 0; off >>= 1)
#pragma unroll
            for (int r = 0; r < RPB; r++)
                val[r] += __shfl_xor_sync(0xffffffffu, val[r], off);

        if ((t & 31) == 0)
#pragma unroll
            for (int r = 0; r < RPB; r++) red[r][t >> 5] = val[r];
    }
    __syncthreads();

    if (t < RPB) {
        const int row = row0 + t;
        float loss = 0.f;
        if (row < B) {
            const float z = (red[t][0] + red[t][1]) +
                            (red[t][2] + red[t][3]) + __ldg(b_out);
            const float lp  = fmaxf(-log1pf(expf(-z)), -100.0f);
            const float l1m = fmaxf(-log1pf(expf(z)),  -100.0f);
            const float y   = __ldg(&y_true[row]);
            loss = -(y * lp + (1.0f - y) * l1m);
        }
#pragma unroll
        for (int off = 2; off > 0; off >>= 1)
            loss += __shfl_xor_sync(0x0000000fu, loss, off);
        if (t == 0) atomicAdd(out, loss);
    }
}

// ---------------------------------------------------------------------------
extern "C" void kernel_launch(void* const* d_in, const int* in_sizes, int n_in,
                              void* d_out, int out_size)
{
    const int*   token_ids = (const int*)d_in[0];
    const int*   seg_ids   = (const int*)d_in[1];
    const float* y_true    = (const float*)d_in[2];
    const float* embed     = (const float*)d_in[3];
    const float* W_hid     = (const float*)d_in[4];
    const float* b_hid     = (const float*)d_in[5];
    const float* W_out     = (const float*)d_in[6];
    const float* b_out     = (const float*)d_in[7];

    const int T = in_sizes[0];
    const int B = in_sizes[2];
    float* out = (float*)d_out;

    seg_mean_kernel<<<B, 128>>>(token_ids, seg_ids, embed, out, T);

    mlp_bce_kernel<<<(B + RPB - 1) / RPB, 256>>>(y_true, W_hid, b_hid,
                                                 W_out, b_out, out, B);
}